// round 10
// baseline (speedup 1.0000x reference)
#include <cuda_runtime.h>
#include <math.h>

// Problem constants
#define NBc   16
#define NAc   5
#define NKc   9
#define NCc   13
#define NHc   38
#define NWc   38
#define MAXTc 50
#define NPIX  (NHc*NWc)        // 1444
#define NANCH (NAc*NPIX)       // 7220
#define NTOTc (NBc*NANCH)      // 115520
#define CHPA  (2*NKc+1+NCc)    // 32
#define TROW  21

#define TPB   128
#define BPB   ((NANCH + TPB - 1)/TPB)  // 57 blocks per batch
#define NBLK  (NBc*BPB)                // 912

#define NTFAST 8                        // unrolled fast path (nv <= 8 here)

// meta record: [0]=tconf, [1]=cls, [2..3]=pad, [4..21]=(gx,gy)*9, [22..39]=(vx,vy)*9
#define MSTRIDE 40

#define SCX   (640.0f/38.0f)
#define SCY   (480.0f/38.0f)
#define DENOM9   57.50150489f
#define STHRESH  34.50090293f   // 0.6 * 9 * (e^2 - 1)
// ssum > STHRESH requires some corner with |dx|,|dy| <= 16.98  ->  17px margin
#define MARGIN   17.0f

__device__ float g_part[NBLK][2];
__device__ int   g_cnt = 0;

__device__ __forceinline__ float sigf(float x) { return 1.0f / (1.0f + __expf(-x)); }

__global__ void __launch_bounds__(TPB, 6)
k_main(const float* __restrict__ out,
       const float* __restrict__ tgt,
       const float* __restrict__ anc,
       const void*  __restrict__ epoch_ptr,
       float* __restrict__ d_out) {
    __shared__ __align__(16) int    s_keys[64];          // target match keys
    __shared__ __align__(16) float4 s_bbox[MAXTc];       // target corner bboxes
    __shared__ __align__(16) float  s_meta[MAXTc*MSTRIDE];
    __shared__ int    s_nv;
    __shared__ float2 s_wred[TPB/32];
    __shared__ bool   s_last;

    const int tid  = threadIdx.x;
    const int lane = tid & 31;
    const int wid  = tid >> 5;
    const int b    = blockIdx.x / BPB;
    const int cell = (blockIdx.x % BPB) * TPB + tid;
    const bool ok  = (cell < NANCH);
    const float* tgb = tgt + (size_t)b * (MAXTc*TROW);

    // ---- per-cell channel loads (early, batched) + P bbox ------------------
    int a = 0, h = 0, w = 0;
    const float* baseo = out;
    float Px[NKc], Py[NKc], confv = 0.0f;
    float pxmin = 1e30f, pxmax = -1e30f, pymin = 1e30f, pymax = -1e30f;
    if (ok) {
        a = cell / NPIX;
        int pix = cell % NPIX;
        h = pix / NWc; w = pix % NWc;
        baseo = out + ((size_t)(b * NAc + a) * CHPA) * NPIX + pix;
        float rc = baseo[(2*NKc) * NPIX];
        #pragma unroll
        for (int k = 0; k < NKc; ++k) {
            float xv = baseo[(2*k)   * NPIX];
            float yv = baseo[(2*k+1) * NPIX];
            if (k == 0) { xv = sigf(xv); yv = sigf(yv); }
            Px[k] = (xv + (float)w) * SCX;
            Py[k] = (yv + (float)h) * SCY;
            pxmin = fminf(pxmin, Px[k]);  pxmax = fmaxf(pxmax, Px[k]);
            pymin = fminf(pymin, Py[k]);  pymax = fmaxf(pymax, Py[k]);
        }
        confv = sigf(rc);
    }
    // expanded P bbox for the overlap test
    const float pxminE = pxmin - MARGIN, pxmaxE = pxmax + MARGIN;
    const float pyminE = pymin - MARGIN, pymaxE = pymax + MARGIN;

    // ---- validity prefix via ballots (warp 0 reads global directly) --------
    if (wid == 0) {
        float v0 = tgb[lane*TROW + 1];
        float v1 = (lane < MAXTc - 32) ? tgb[(lane+32)*TROW + 1] : 0.0f;
        unsigned m0 = __ballot_sync(0xFFFFFFFFu, v0 != 0.0f);
        unsigned m1 = __ballot_sync(0xFFFFFFFFu, v1 != 0.0f);
        if (lane == 0) {
            int nv;
            if (~m0) nv = __ffs(~m0) - 1;
            else {
                unsigned inv = (~m1) & ((1u << (MAXTc - 32)) - 1u);
                nv = inv ? 32 + __ffs(inv) - 1 : MAXTc;
            }
            s_nv = nv;
        }
    }
    __syncthreads();
    const int nv = s_nv;

    // ---- per-target meta straight from global -> shared --------------------
    if (tid < nv) {
        const int t = tid;
        const float* tb = tgb + t*TROW;
        float* mr = &s_meta[t*MSTRIDE];

        float gw = tb[19] * (float)NWc;
        float gh = tb[20] * (float)NHc;
        float best = -1.0f; int bn = 0;
        #pragma unroll
        for (int aa = 0; aa < NAc; ++aa) {
            float aw = anc[2*aa], ah = anc[2*aa+1];
            float cw = fminf(gw, aw), ch = fminf(gh, ah);
            float iou = 0.0f;
            if (cw > 0.0f && ch > 0.0f) {
                float ca = cw * ch;
                iou = ca / (gw * gh + aw * ah - ca);
            }
            if (iou > best) { best = iou; bn = aa; }
        }
        int gi0 = (int)floorf(tb[1] * (float)NWc);
        int gj0 = (int)floorf(tb[2] * (float)NHc);
        s_keys[t] = (bn << 12) | (gj0 << 6) | gi0;
        mr[1] = tb[0];

        float gxp[NKc], gyp[NKc];
        float xmn = 1e30f, xmx = -1e30f, ymn = 1e30f, ymx = -1e30f;
        #pragma unroll
        for (int k = 0; k < NKc; ++k) {
            float gx = tb[1 + 2*k], gy = tb[2 + 2*k];
            gxp[k] = gx * 640.0f;  gyp[k] = gy * 480.0f;
            xmn = fminf(xmn, gxp[k]);  xmx = fmaxf(xmx, gxp[k]);
            ymn = fminf(ymn, gyp[k]);  ymx = fmaxf(ymx, gyp[k]);
            mr[4  + 2*k] = gxp[k];
            mr[5  + 2*k] = gyp[k];
            mr[22 + 2*k] = gx * (float)NWc - (float)gi0;
            mr[23 + 2*k] = gy * (float)NHc - (float)gj0;
        }
        s_bbox[t] = make_float4(xmn, xmx, ymn, ymx);

        // tconf at pidx-shifted cell
        long long p = (long long)b * NANCH - NPIX + (long long)gj0 * NWc + gi0;
        const long long tot = NTOTc;
        p = ((p % tot) + tot) % tot;
        int b2  = (int)(p / NANCH);
        int rem = (int)(p % NANCH);
        int a2  = rem / NPIX;
        int px2 = rem % NPIX;
        int h2 = px2 / NWc, w2 = px2 % NWc;
        const float* bo2 = out + ((size_t)(b2 * NAc + a2) * CHPA) * NPIX + px2;

        float s = 0.0f;
        #pragma unroll
        for (int k = 0; k < NKc; ++k) {
            float xv = bo2[(2*k)   * NPIX];
            float yv = bo2[(2*k+1) * NPIX];
            if (k == 0) { xv = sigf(xv); yv = sigf(yv); }
            float qx = (xv + (float)w2) * SCX;
            float qy = (yv + (float)h2) * SCY;
            float dx = gxp[k] - qx;
            float dy = gyp[k] - qy;
            float d2 = fmaf(dx, dx, dy * dy);
            if (d2 < 6400.0f) s += __expf(2.0f - sqrtf(d2) * 0.025f) - 1.0f;
        }
        mr[0] = s * (1.0f / DENOM9);
    } else if (tid < NTFAST) {
        // sentinel: never matches, never overlaps
        s_keys[tid] = 0x7FFFFFFF;
        s_bbox[tid] = make_float4(1e30f, -1e30f, 1e30f, -1e30f);
    }
    __syncthreads();

    // ---- scan: key match + bbox overlap test (branch-free, unrolled) -------
    float baseLoss = 0.0f, confLoss = 0.0f;

    if (ok) {
        const int mykey = (a << 12) | (h << 6) | w;
        const int4 kA = *(const int4*)&s_keys[0];
        const int4 kB = *(const int4*)&s_keys[4];
        int m = -1;
        if (kA.x == mykey) m = 0;
        if (kA.y == mykey) m = 1;
        if (kA.z == mykey) m = 2;
        if (kA.w == mykey) m = 3;
        if (kB.x == mykey) m = 4;
        if (kB.y == mykey) m = 5;
        if (kB.z == mykey) m = 6;
        if (kB.w == mykey) m = 7;

        unsigned gatemask = 0;
        #pragma unroll
        for (int t = 0; t < NTFAST; ++t) {
            float4 bb = s_bbox[t];     // LDS.128, warp-broadcast
            bool ov = (bb.y >= pxminE) & (bb.x <= pxmaxE)
                    & (bb.w >= pyminE) & (bb.z <= pymaxE);
            gatemask |= ov ? (1u << t) : 0u;
        }
        // dynamic tail (nv > 8 — defensive; not hit for this generator)
        int silent = 0;
        for (int t = NTFAST; t < nv; ++t) {
            if (s_keys[t] == mykey) m = t;
            float4 bb = s_bbox[t];
            if ((bb.y >= pxminE) & (bb.x <= pxmaxE)
              & (bb.w >= pyminE) & (bb.z <= pymaxE))
                gatemask |= (1u << (t & 31));   // just force evaluation below
        }

        if (m >= 0) {
            // matched cell (rare): coord + CE + obj-conf
            const float* mr = &s_meta[m*MSTRIDE];
            #pragma unroll
            for (int k = 0; k < NKc; ++k) {
                float xv = baseo[(2*k)   * NPIX];
                float yv = baseo[(2*k+1) * NPIX];
                if (k == 0) { xv = sigf(xv); yv = sigf(yv); }
                float dx = xv - mr[22 + 2*k];
                float dy = yv - mr[23 + 2*k];
                baseLoss += 0.5f * (dx*dx + dy*dy);
            }
            float mx = -1e30f;
            #pragma unroll
            for (int c = 0; c < NCc; ++c)
                mx = fmaxf(mx, baseo[(2*NKc + 1 + c) * NPIX]);
            float se = 0.0f;
            #pragma unroll
            for (int c = 0; c < NCc; ++c)
                se += __expf(baseo[(2*NKc + 1 + c) * NPIX] - mx);
            int lab = (int)mr[1];
            lab = lab < 0 ? 0 : (lab > NCc - 1 ? NCc - 1 : lab);
            baseLoss += __logf(se) + mx - baseo[(2*NKc + 1 + lab) * NPIX];
            float dc = confv - mr[0];
            confLoss = 2.5f * dc * dc;
        } else {
            // exact evaluation of overlapping targets only (rare)
            if (nv > NTFAST) {
                // defensive slow path: evaluate all targets exactly
                for (int t = 0; t < nv && !silent; ++t) {
                    const float2* gp = (const float2*)(s_meta + t*MSTRIDE + 4);
                    float ssum = 0.0f;
                    #pragma unroll
                    for (int k = 0; k < NKc; ++k) {
                        float dx = Px[k] - gp[k].x;
                        float dy = Py[k] - gp[k].y;
                        float d2 = fmaf(dx, dx, dy * dy);
                        if (d2 < 6400.0f)
                            ssum += __expf(2.0f - sqrtf(d2) * 0.025f) - 1.0f;
                    }
                    if (ssum > STHRESH) silent = 1;
                }
            } else {
                while (gatemask && !silent) {
                    int t = __ffs(gatemask) - 1;
                    gatemask &= gatemask - 1;
                    const float2* gp = (const float2*)(s_meta + t*MSTRIDE + 4);
                    float ssum = 0.0f;
                    #pragma unroll
                    for (int k = 0; k < NKc; ++k) {
                        float dx = Px[k] - gp[k].x;
                        float dy = Py[k] - gp[k].y;
                        float d2 = fmaf(dx, dx, dy * dy);
                        if (d2 < 6400.0f)
                            ssum += __expf(2.0f - sqrtf(d2) * 0.025f) - 1.0f;
                    }
                    if (ssum > STHRESH) silent = 1;
                }
            }
            if (!silent) confLoss = 0.5f * confv * confv;
        }
    }

    // ---- block reduction ----------------------------------------------------
    float v0 = baseLoss, v1 = confLoss;
    #pragma unroll
    for (int o = 16; o > 0; o >>= 1) {
        v0 += __shfl_down_sync(0xFFFFFFFFu, v0, o);
        v1 += __shfl_down_sync(0xFFFFFFFFu, v1, o);
    }
    if (lane == 0) s_wred[wid] = make_float2(v0, v1);
    __syncthreads();
    if (tid == 0) {
        float rb = 0.0f, rc = 0.0f;
        #pragma unroll
        for (int j = 0; j < TPB/32; ++j) { rb += s_wred[j].x; rc += s_wred[j].y; }
        g_part[blockIdx.x][0] = rb;
        g_part[blockIdx.x][1] = rc;
    }

    // ---- last-block-done final reduction ------------------------------------
    __threadfence();
    if (tid == 0) {
        int old = atomicAdd(&g_cnt, 1);
        s_last = (old == NBLK - 1);
    }
    __syncthreads();
    if (!s_last) return;

    float rb = 0.0f, rc = 0.0f;
    for (int idx = tid; idx < NBLK; idx += TPB) {
        rb += g_part[idx][0];
        rc += g_part[idx][1];
    }
    #pragma unroll
    for (int o = 16; o > 0; o >>= 1) {
        rb += __shfl_down_sync(0xFFFFFFFFu, rb, o);
        rc += __shfl_down_sync(0xFFFFFFFFu, rc, o);
    }
    if (lane == 0) s_wred[wid] = make_float2(rb, rc);
    __syncthreads();
    if (tid == 0) {
        float tb2 = 0.0f, tc2 = 0.0f;
        #pragma unroll
        for (int j = 0; j < TPB/32; ++j) { tb2 += s_wred[j].x; tc2 += s_wred[j].y; }
        int ev = ((const int*)epoch_ptr)[0];
        if (ev > 1000000 || ev < -1000000) ev = (int)__int_as_float(ev);
        float total = tb2;
        if (ev > 15) total += tc2;
        d_out[0] = total;
        g_cnt = 0;   // reset for graph replay
    }
}

extern "C" void kernel_launch(void* const* d_in, const int* in_sizes, int n_in,
                              void* d_out, int out_size) {
    const float* out_t = (const float*)d_in[0];
    const float* tgt   = (const float*)d_in[1];
    const float* anc   = (const float*)d_in[2];
    const void*  epoch = d_in[3];
    k_main<<<NBLK, TPB>>>(out_t, tgt, anc, epoch, (float*)d_out);
}

// round 11
// speedup vs baseline: 1.2183x; 1.2183x over previous
#include <cuda_runtime.h>
#include <math.h>

// Problem constants
#define NBc   16
#define NAc   5
#define NKc   9
#define NCc   13
#define NHc   38
#define NWc   38
#define MAXTc 50
#define NPIX  (NHc*NWc)        // 1444
#define NANCH (NAc*NPIX)       // 7220
#define NTOTc (NBc*NANCH)      // 115520
#define CHPA  (2*NKc+1+NCc)    // 32
#define TROW  21

#define TPB   256
#define BPB   ((NANCH + TPB - 1)/TPB)  // 29 blocks per batch
#define NBLK  (NBc*BPB)                // 464 blocks

#define SCX   (640.0f/38.0f)
#define SCY   (480.0f/38.0f)
#define DENOM9   57.50150489f
#define STHRESH  34.50090293f   // 0.6 * 9 * (e^2 - 1)
// ssum > STHRESH requires max corner term >= STHRESH/9 -> some d2 < 288.12
#define GATE2    290.0f

__device__ float g_part[NBLK][2];
__device__ int   g_cnt = 0;

__device__ __forceinline__ float sigf(float x) { return 1.0f / (1.0f + __expf(-x)); }

__global__ void __launch_bounds__(TPB)
k_main(const float* __restrict__ out,
       const float* __restrict__ tgt,
       const float* __restrict__ anc,
       const void*  __restrict__ epoch_ptr,
       float* __restrict__ d_out) {
    __shared__ int    s_nv;
    __shared__ int    s_key[MAXTc];
    __shared__ float  s_tconf[MAXTc], s_cls[MAXTc];
    __shared__ __align__(16) float2 s_g[MAXTc*NKc];   // corner px coords
    __shared__ __align__(16) float2 s_v[MAXTc*NKc];   // coord targets
    __shared__ float2 s_wred[TPB/32];
    __shared__ bool   s_last;

    const int tid  = threadIdx.x;
    const int lane = tid & 31;
    const int wid  = tid >> 5;
    const int b    = blockIdx.x / BPB;
    const int cell = (blockIdx.x % BPB) * TPB + tid;
    const bool ok  = (cell < NANCH);
    const float* tgb = tgt + (size_t)b * (MAXTc*TROW);

    // ---- per-cell channel loads, issued early; fold into Px/Py -------------
    int a = 0, h = 0, w = 0;
    const float* baseo = out;
    float Px[NKc], Py[NKc], confv = 0.0f;
    if (ok) {
        a = cell / NPIX;
        int pix = cell % NPIX;
        h = pix / NWc; w = pix % NWc;
        baseo = out + ((size_t)(b * NAc + a) * CHPA) * NPIX + pix;
        float rc = baseo[(2*NKc) * NPIX];
        #pragma unroll
        for (int k = 0; k < NKc; ++k) {
            float xv = baseo[(2*k)   * NPIX];
            float yv = baseo[(2*k+1) * NPIX];
            if (k == 0) { xv = sigf(xv); yv = sigf(yv); }
            Px[k] = (xv + (float)w) * SCX;
            Py[k] = (yv + (float)h) * SCY;
        }
        confv = sigf(rc);
    }

    // ---- validity prefix via ballots (warp 0 reads global directly) --------
    if (wid == 0) {
        float v0 = tgb[lane*TROW + 1];
        float v1 = (lane < MAXTc - 32) ? tgb[(lane+32)*TROW + 1] : 0.0f;
        unsigned m0 = __ballot_sync(0xFFFFFFFFu, v0 != 0.0f);
        unsigned m1 = __ballot_sync(0xFFFFFFFFu, v1 != 0.0f);
        if (lane == 0) {
            int nv;
            if (~m0) nv = __ffs(~m0) - 1;
            else {
                unsigned inv = (~m1) & ((1u << (MAXTc - 32)) - 1u);
                nv = inv ? 32 + __ffs(inv) - 1 : MAXTc;
            }
            s_nv = nv;
        }
    }
    // meta threads read targets from global directly (L2/L1-hot across blocks)
    __syncthreads();
    const int nv = s_nv;

    // ---- per-target meta -> shared -----------------------------------------
    if (tid < nv) {
        const int t = tid;
        const float* tb = tgb + t*TROW;

        float gw = tb[19] * (float)NWc;
        float gh = tb[20] * (float)NHc;
        float best = -1.0f; int bn = 0;
        #pragma unroll
        for (int aa = 0; aa < NAc; ++aa) {
            float aw = anc[2*aa], ah = anc[2*aa+1];
            float cw = fminf(gw, aw), ch = fminf(gh, ah);
            float iou = 0.0f;
            if (cw > 0.0f && ch > 0.0f) {
                float ca = cw * ch;
                iou = ca / (gw * gh + aw * ah - ca);
            }
            if (iou > best) { best = iou; bn = aa; }
        }
        int gi0 = (int)floorf(tb[1] * (float)NWc);
        int gj0 = (int)floorf(tb[2] * (float)NHc);
        s_key[t] = (bn << 12) | (gj0 << 6) | gi0;
        s_cls[t] = tb[0];

        float gxp[NKc], gyp[NKc];
        #pragma unroll
        for (int k = 0; k < NKc; ++k) {
            float gx = tb[1 + 2*k], gy = tb[2 + 2*k];
            gxp[k] = gx * 640.0f;  gyp[k] = gy * 480.0f;
            s_g[t*NKc + k] = make_float2(gxp[k], gyp[k]);
            s_v[t*NKc + k] = make_float2(gx * (float)NWc - (float)gi0,
                                         gy * (float)NHc - (float)gj0);
        }

        // tconf at pidx-shifted cell
        long long p = (long long)b * NANCH - NPIX + (long long)gj0 * NWc + gi0;
        const long long tot = NTOTc;
        p = ((p % tot) + tot) % tot;
        int b2  = (int)(p / NANCH);
        int rem = (int)(p % NANCH);
        int a2  = rem / NPIX;
        int px2 = rem % NPIX;
        int h2 = px2 / NWc, w2 = px2 % NWc;
        const float* bo2 = out + ((size_t)(b2 * NAc + a2) * CHPA) * NPIX + px2;

        float s = 0.0f;
        #pragma unroll
        for (int k = 0; k < NKc; ++k) {
            float xv = bo2[(2*k)   * NPIX];
            float yv = bo2[(2*k+1) * NPIX];
            if (k == 0) { xv = sigf(xv); yv = sigf(yv); }
            float qx = (xv + (float)w2) * SCX;
            float qy = (yv + (float)h2) * SCY;
            float dx = gxp[k] - qx;
            float dy = gyp[k] - qy;
            float d2 = fmaf(dx, dx, dy * dy);
            if (d2 < 6400.0f) s += __expf(2.0f - sqrtf(d2) * 0.025f) - 1.0f;
        }
        s_tconf[t] = s * (1.0f / DENOM9);
    }
    __syncthreads();

    // ---- per-cell loss ------------------------------------------------------
    float baseLoss = 0.0f, confLoss = 0.0f;

    if (ok) {
        const int mykey = (a << 12) | (h << 6) | w;
        int m = -1;
        for (int t = 0; t < nv; ++t)
            if (s_key[t] == mykey) m = t;

        if (m >= 0) {
            // matched (rare): coord + CE + obj-conf
            #pragma unroll
            for (int k = 0; k < NKc; ++k) {
                float xv = baseo[(2*k)   * NPIX];
                float yv = baseo[(2*k+1) * NPIX];
                if (k == 0) { xv = sigf(xv); yv = sigf(yv); }
                float2 v = s_v[m*NKc + k];
                float dx = xv - v.x;
                float dy = yv - v.y;
                baseLoss += 0.5f * (dx*dx + dy*dy);
            }
            float mx = -1e30f;
            #pragma unroll
            for (int c = 0; c < NCc; ++c)
                mx = fmaxf(mx, baseo[(2*NKc + 1 + c) * NPIX]);
            float se = 0.0f;
            #pragma unroll
            for (int c = 0; c < NCc; ++c)
                se += __expf(baseo[(2*NKc + 1 + c) * NPIX] - mx);
            int lab = (int)s_cls[m];
            lab = lab < 0 ? 0 : (lab > NCc - 1 ? NCc - 1 : lab);
            baseLoss += __logf(se) + mx - baseo[(2*NKc + 1 + lab) * NPIX];
            float dc = confv - s_tconf[m];
            confLoss = 2.5f * dc * dc;
        } else {
            // silence check with exact-necessary gate d2min < 290
            bool silent = false;
            for (int t = 0; t < nv; ++t) {
                float d2[NKc];
                #pragma unroll
                for (int k = 0; k < NKc; ++k) {
                    float2 g = s_g[t*NKc + k];
                    float dx = Px[k] - g.x;
                    float dy = Py[k] - g.y;
                    d2[k] = fmaf(dx, dx, dy * dy);
                }
                float m01 = fminf(d2[0], d2[1]), m23 = fminf(d2[2], d2[3]);
                float m45 = fminf(d2[4], d2[5]), m67 = fminf(d2[6], d2[7]);
                float dmin = fminf(fminf(fminf(m01, m23), fminf(m45, m67)), d2[8]);
                if (dmin < GATE2) {            // rare (~2-3% of pairs)
                    float ssum = 0.0f;
                    #pragma unroll
                    for (int k = 0; k < NKc; ++k)
                        if (d2[k] < 6400.0f)
                            ssum += __expf(2.0f - sqrtf(d2[k]) * 0.025f) - 1.0f;
                    if (ssum > STHRESH) { silent = true; break; }
                }
            }
            if (!silent) confLoss = 0.5f * confv * confv;
        }
    }

    // ---- block reduction ----------------------------------------------------
    float v0 = baseLoss, v1 = confLoss;
    #pragma unroll
    for (int o = 16; o > 0; o >>= 1) {
        v0 += __shfl_down_sync(0xFFFFFFFFu, v0, o);
        v1 += __shfl_down_sync(0xFFFFFFFFu, v1, o);
    }
    if (lane == 0) s_wred[wid] = make_float2(v0, v1);
    __syncthreads();
    if (tid == 0) {
        float rb = 0.0f, rc = 0.0f;
        #pragma unroll
        for (int j = 0; j < TPB/32; ++j) { rb += s_wred[j].x; rc += s_wred[j].y; }
        g_part[blockIdx.x][0] = rb;
        g_part[blockIdx.x][1] = rc;
    }

    // ---- last-block-done final reduction ------------------------------------
    __threadfence();
    if (tid == 0) {
        int old = atomicAdd(&g_cnt, 1);
        s_last = (old == NBLK - 1);
    }
    __syncthreads();
    if (!s_last) return;

    float rb = 0.0f, rc = 0.0f;
    for (int idx = tid; idx < NBLK; idx += TPB) {
        rb += g_part[idx][0];
        rc += g_part[idx][1];
    }
    #pragma unroll
    for (int o = 16; o > 0; o >>= 1) {
        rb += __shfl_down_sync(0xFFFFFFFFu, rb, o);
        rc += __shfl_down_sync(0xFFFFFFFFu, rc, o);
    }
    if (lane == 0) s_wred[wid] = make_float2(rb, rc);
    __syncthreads();
    if (tid == 0) {
        float tb2 = 0.0f, tc2 = 0.0f;
        #pragma unroll
        for (int j = 0; j < TPB/32; ++j) { tb2 += s_wred[j].x; tc2 += s_wred[j].y; }
        int ev = ((const int*)epoch_ptr)[0];
        if (ev > 1000000 || ev < -1000000) ev = (int)__int_as_float(ev);
        float total = tb2;
        if (ev > 15) total += tc2;
        d_out[0] = total;
        g_cnt = 0;   // reset for graph replay
    }
}

extern "C" void kernel_launch(void* const* d_in, const int* in_sizes, int n_in,
                              void* d_out, int out_size) {
    const float* out_t = (const float*)d_in[0];
    const float* tgt   = (const float*)d_in[1];
    const float* anc   = (const float*)d_in[2];
    const void*  epoch = d_in[3];
    k_main<<<NBLK, TPB>>>(out_t, tgt, anc, epoch, (float*)d_out);
}

// round 12
// speedup vs baseline: 1.2206x; 1.0019x over previous
#include <cuda_runtime.h>
#include <math.h>

// Problem constants
#define NBc   16
#define NAc   5
#define NKc   9
#define NCc   13
#define NHc   38
#define NWc   38
#define MAXTc 50
#define NPIX  (NHc*NWc)        // 1444
#define NANCH (NAc*NPIX)       // 7220
#define NTOTc (NBc*NANCH)      // 115520
#define CHPA  (2*NKc+1+NCc)    // 32
#define TROW  21

#define TPB   256
#define BPB   ((NANCH + TPB - 1)/TPB)  // 29 blocks per batch
#define NBLK  (NBc*BPB)                // 464 blocks

#define SCX   (640.0f/38.0f)
#define SCY   (480.0f/38.0f)
#define DENOM9   57.50150489f
#define STHRESH  34.50090293f   // 0.6 * 9 * (e^2 - 1)
// ssum > STHRESH requires max corner term >= STHRESH/9 -> some d2 < 288.12
#define GATE2    290.0f

__device__ float g_part[NBLK][2];
__device__ int   g_cnt = 0;

__device__ __forceinline__ float sigf(float x) { return 1.0f / (1.0f + __expf(-x)); }

__global__ void __launch_bounds__(TPB, 3)
k_main(const float* __restrict__ out,
       const float* __restrict__ tgt,
       const float* __restrict__ anc,
       const void*  __restrict__ epoch_ptr,
       float* __restrict__ d_out) {
    __shared__ int    s_nv;
    __shared__ int    s_key[MAXTc];
    __shared__ float  s_cls[MAXTc];
    __shared__ __align__(16) float4 s_gq[MAXTc][5];   // corners packed (10 f2 slots)
    __shared__ __align__(16) float2 s_v[MAXTc*NKc];   // coord targets
    __shared__ float2 s_wred[TPB/32];
    __shared__ bool   s_last;

    const int tid  = threadIdx.x;
    const int lane = tid & 31;
    const int wid  = tid >> 5;
    const int b    = blockIdx.x / BPB;
    const int cell = (blockIdx.x % BPB) * TPB + tid;
    const bool ok  = (cell < NANCH);
    const float* tgb = tgt + (size_t)b * (MAXTc*TROW);

    // ---- preload target row for meta threads (issue loads early) ------------
    float tb[TROW];
    if (tid < MAXTc) {
        #pragma unroll
        for (int i = 0; i < TROW; ++i) tb[i] = tgb[tid*TROW + i];
    }

    // ---- per-cell channel loads; fold into Px/Py ----------------------------
    int a = 0, h = 0, w = 0;
    const float* baseo = out;
    float Px[NKc], Py[NKc], confv = 0.0f;
    if (ok) {
        a = cell / NPIX;
        int pix = cell % NPIX;
        h = pix / NWc; w = pix % NWc;
        baseo = out + ((size_t)(b * NAc + a) * CHPA) * NPIX + pix;
        float rc = baseo[(2*NKc) * NPIX];
        #pragma unroll
        for (int k = 0; k < NKc; ++k) {
            float xv = baseo[(2*k)   * NPIX];
            float yv = baseo[(2*k+1) * NPIX];
            if (k == 0) { xv = sigf(xv); yv = sigf(yv); }
            Px[k] = (xv + (float)w) * SCX;
            Py[k] = (yv + (float)h) * SCY;
        }
        confv = sigf(rc);
    }

    // ---- validity prefix via ballots (warp 0) -------------------------------
    if (wid == 0) {
        float v0 = tgb[lane*TROW + 1];                 // L1 hit (preloaded above)
        float v1 = (lane < MAXTc - 32) ? tgb[(lane+32)*TROW + 1] : 0.0f;
        unsigned m0 = __ballot_sync(0xFFFFFFFFu, v0 != 0.0f);
        unsigned m1 = __ballot_sync(0xFFFFFFFFu, v1 != 0.0f);
        if (lane == 0) {
            int nv;
            if (~m0) nv = __ffs(~m0) - 1;
            else {
                unsigned inv = (~m1) & ((1u << (MAXTc - 32)) - 1u);
                nv = inv ? 32 + __ffs(inv) - 1 : MAXTc;
            }
            s_nv = nv;
        }
    }

    // ---- per-target meta (cheap now: NO tconf loads) ------------------------
    if (tid < MAXTc && tb[1] != 0.0f) {
        const int t = tid;
        float gw = tb[19] * (float)NWc;
        float gh = tb[20] * (float)NHc;
        float best = -1.0f; int bn = 0;
        #pragma unroll
        for (int aa = 0; aa < NAc; ++aa) {
            float aw = anc[2*aa], ah = anc[2*aa+1];
            float cw = fminf(gw, aw), ch = fminf(gh, ah);
            float iou = 0.0f;
            if (cw > 0.0f && ch > 0.0f) {
                float ca = cw * ch;
                iou = ca / (gw * gh + aw * ah - ca);
            }
            if (iou > best) { best = iou; bn = aa; }
        }
        int gi0 = (int)floorf(tb[1] * (float)NWc);
        int gj0 = (int)floorf(tb[2] * (float)NHc);
        s_key[t] = (bn << 12) | (gj0 << 6) | gi0;
        s_cls[t] = tb[0];

        float* gq = (float*)&s_gq[t][0];
        #pragma unroll
        for (int k = 0; k < NKc; ++k) {
            float gx = tb[1 + 2*k], gy = tb[2 + 2*k];
            gq[2*k]   = gx * 640.0f;
            gq[2*k+1] = gy * 480.0f;
            s_v[t*NKc + k] = make_float2(gx * (float)NWc - (float)gi0,
                                         gy * (float)NHc - (float)gj0);
        }
        gq[18] = 1.0e9f;  gq[19] = 1.0e9f;   // sentinel 10th corner
    }
    __syncthreads();
    const int nv = s_nv;

    // ---- per-cell loss ------------------------------------------------------
    float baseLoss = 0.0f, confLoss = 0.0f;

    if (ok) {
        const int mykey = (a << 12) | (h << 6) | w;
        int m = -1;
        for (int t = 0; t < nv; ++t)
            if (s_key[t] == mykey) m = t;

        if (m >= 0) {
            // matched (rare): coord + CE + obj-conf (incl. own tconf compute)
            #pragma unroll
            for (int k = 0; k < NKc; ++k) {
                float xv = baseo[(2*k)   * NPIX];
                float yv = baseo[(2*k+1) * NPIX];
                if (k == 0) { xv = sigf(xv); yv = sigf(yv); }
                float2 v = s_v[m*NKc + k];
                float dx = xv - v.x;
                float dy = yv - v.y;
                baseLoss += 0.5f * (dx*dx + dy*dy);
            }
            float mx = -1e30f;
            #pragma unroll
            for (int c = 0; c < NCc; ++c)
                mx = fmaxf(mx, baseo[(2*NKc + 1 + c) * NPIX]);
            float se = 0.0f;
            #pragma unroll
            for (int c = 0; c < NCc; ++c)
                se += __expf(baseo[(2*NKc + 1 + c) * NPIX] - mx);
            int lab = (int)s_cls[m];
            lab = lab < 0 ? 0 : (lab > NCc - 1 ? NCc - 1 : lab);
            baseLoss += __logf(se) + mx - baseo[(2*NKc + 1 + lab) * NPIX];

            // ---- tconf for this target, computed here (rare path) ----------
            int gi0 = mykey & 63, gj0 = (mykey >> 6) & 63;
            long long p = (long long)b * NANCH - NPIX + (long long)gj0 * NWc + gi0;
            const long long tot = NTOTc;
            p = ((p % tot) + tot) % tot;
            int b2  = (int)(p / NANCH);
            int rem = (int)(p % NANCH);
            int a2  = rem / NPIX;
            int px2 = rem % NPIX;
            int h2 = px2 / NWc, w2 = px2 % NWc;
            const float* bo2 = out + ((size_t)(b2 * NAc + a2) * CHPA) * NPIX + px2;
            const float* gq = (const float*)&s_gq[m][0];
            float s = 0.0f;
            #pragma unroll
            for (int k = 0; k < NKc; ++k) {
                float xv = bo2[(2*k)   * NPIX];
                float yv = bo2[(2*k+1) * NPIX];
                if (k == 0) { xv = sigf(xv); yv = sigf(yv); }
                float qx = (xv + (float)w2) * SCX;
                float qy = (yv + (float)h2) * SCY;
                float dx = gq[2*k]   - qx;
                float dy = gq[2*k+1] - qy;
                float d2 = fmaf(dx, dx, dy * dy);
                if (d2 < 6400.0f) s += __expf(2.0f - sqrtf(d2) * 0.025f) - 1.0f;
            }
            float tconf = s * (1.0f / DENOM9);
            float dc = confv - tconf;
            confLoss = 2.5f * dc * dc;
        } else {
            // silence check: float4 corner loads + exact-necessary gate
            bool silent = false;
            for (int t = 0; t < nv; ++t) {
                float4 q0 = s_gq[t][0];
                float4 q1 = s_gq[t][1];
                float4 q2 = s_gq[t][2];
                float4 q3 = s_gq[t][3];
                float4 q4 = s_gq[t][4];
                float d2[NKc];
                { float dx = Px[0]-q0.x, dy = Py[0]-q0.y; d2[0] = fmaf(dx,dx,dy*dy); }
                { float dx = Px[1]-q0.z, dy = Py[1]-q0.w; d2[1] = fmaf(dx,dx,dy*dy); }
                { float dx = Px[2]-q1.x, dy = Py[2]-q1.y; d2[2] = fmaf(dx,dx,dy*dy); }
                { float dx = Px[3]-q1.z, dy = Py[3]-q1.w; d2[3] = fmaf(dx,dx,dy*dy); }
                { float dx = Px[4]-q2.x, dy = Py[4]-q2.y; d2[4] = fmaf(dx,dx,dy*dy); }
                { float dx = Px[5]-q2.z, dy = Py[5]-q2.w; d2[5] = fmaf(dx,dx,dy*dy); }
                { float dx = Px[6]-q3.x, dy = Py[6]-q3.y; d2[6] = fmaf(dx,dx,dy*dy); }
                { float dx = Px[7]-q3.z, dy = Py[7]-q3.w; d2[7] = fmaf(dx,dx,dy*dy); }
                { float dx = Px[8]-q4.x, dy = Py[8]-q4.y; d2[8] = fmaf(dx,dx,dy*dy); }
                float m01 = fminf(d2[0], d2[1]), m23 = fminf(d2[2], d2[3]);
                float m45 = fminf(d2[4], d2[5]), m67 = fminf(d2[6], d2[7]);
                float dmin = fminf(fminf(fminf(m01, m23), fminf(m45, m67)), d2[8]);
                if (dmin < GATE2) {            // rare (~2-3% of pairs)
                    float ssum = 0.0f;
                    #pragma unroll
                    for (int k = 0; k < NKc; ++k)
                        if (d2[k] < 6400.0f)
                            ssum += __expf(2.0f - sqrtf(d2[k]) * 0.025f) - 1.0f;
                    if (ssum > STHRESH) { silent = true; break; }
                }
            }
            if (!silent) confLoss = 0.5f * confv * confv;
        }
    }

    // ---- block reduction ----------------------------------------------------
    float v0 = baseLoss, v1 = confLoss;
    #pragma unroll
    for (int o = 16; o > 0; o >>= 1) {
        v0 += __shfl_down_sync(0xFFFFFFFFu, v0, o);
        v1 += __shfl_down_sync(0xFFFFFFFFu, v1, o);
    }
    if (lane == 0) s_wred[wid] = make_float2(v0, v1);
    __syncthreads();
    if (tid == 0) {
        float rb = 0.0f, rc = 0.0f;
        #pragma unroll
        for (int j = 0; j < TPB/32; ++j) { rb += s_wred[j].x; rc += s_wred[j].y; }
        g_part[blockIdx.x][0] = rb;
        g_part[blockIdx.x][1] = rc;
    }

    // ---- last-block-done final reduction ------------------------------------
    __threadfence();
    if (tid == 0) {
        int old = atomicAdd(&g_cnt, 1);
        s_last = (old == NBLK - 1);
    }
    __syncthreads();
    if (!s_last) return;

    float rb = 0.0f, rc = 0.0f;
    for (int idx = tid; idx < NBLK; idx += TPB) {
        rb += g_part[idx][0];
        rc += g_part[idx][1];
    }
    #pragma unroll
    for (int o = 16; o > 0; o >>= 1) {
        rb += __shfl_down_sync(0xFFFFFFFFu, rb, o);
        rc += __shfl_down_sync(0xFFFFFFFFu, rc, o);
    }
    if (lane == 0) s_wred[wid] = make_float2(rb, rc);
    __syncthreads();
    if (tid == 0) {
        float tb2 = 0.0f, tc2 = 0.0f;
        #pragma unroll
        for (int j = 0; j < TPB/32; ++j) { tb2 += s_wred[j].x; tc2 += s_wred[j].y; }
        int ev = ((const int*)epoch_ptr)[0];
        if (ev > 1000000 || ev < -1000000) ev = (int)__int_as_float(ev);
        float total = tb2;
        if (ev > 15) total += tc2;
        d_out[0] = total;
        g_cnt = 0;   // reset for graph replay
    }
}

extern "C" void kernel_launch(void* const* d_in, const int* in_sizes, int n_in,
                              void* d_out, int out_size) {
    const float* out_t = (const float*)d_in[0];
    const float* tgt   = (const float*)d_in[1];
    const float* anc   = (const float*)d_in[2];
    const void*  epoch = d_in[3];
    k_main<<<NBLK, TPB>>>(out_t, tgt, anc, epoch, (float*)d_out);
}